// round 1
// baseline (speedup 1.0000x reference)
#include <cuda_runtime.h>
#include <math.h>

// Problem constants
#define BDIM   64     // input dim D
#define H1DIM  128
#define H2DIM  32
#define GRP    8
#define FPG    8
#define EDIM   4
#define ADIM   8
#define HEADS  2
#define OUTD   2

#define TPB 128

// Packed Blackwell f32x2 FMA: d = a*b + c (two fp32 lanes per instruction)
__device__ __forceinline__ float2 ffma2(float2 a, float2 b, float2 c) {
    float2 d;
    asm("fma.rn.f32x2 %0, %1, %2, %3;"
        : "=l"(reinterpret_cast<unsigned long long&>(d))
        : "l"(reinterpret_cast<unsigned long long&>(a)),
          "l"(reinterpret_cast<unsigned long long&>(b)),
          "l"(reinterpret_cast<unsigned long long&>(c)));
    return d;
}

// Shared memory layout (floats)
#define OFF_W1T   0        // [128][64] transposed w1 (w1t[i][f] = w1[f][i])
#define OFF_W2    8192     // [128][32]
#define OFF_B1    12288    // 128
#define OFF_B2    12416    // 32
#define OFF_ENCW  12448    // 256  (g*32 + f*4 + e)
#define OFF_ENCB  12704    // 32
#define OFF_SRCW  12736    // 64   (e*16 + o)
#define OFF_SRCB  12800    // 16
#define OFF_DSTW  12816    // 64
#define OFF_DSTB  12880    // 16
#define OFF_DECW  12896    // 192  (r*2 + c)
#define OFF_DECB  13088    // 2
#define OFF_MEAN  13090    // 64
#define OFF_ISTD  13154    // 64
#define SMEM_FLOATS 13218
#define SMEM_BYTES (SMEM_FLOATS * 4)

__global__ void __launch_bounds__(TPB)
ggan_kernel(const float* __restrict__ x,
            const float* __restrict__ norm_mean,
            const float* __restrict__ norm_std,
            const float* __restrict__ mlp_w1,
            const float* __restrict__ mlp_b1,
            const float* __restrict__ mlp_w2,
            const float* __restrict__ mlp_b2,
            const float* __restrict__ enc_w,
            const float* __restrict__ enc_b,
            const float* __restrict__ src_w,
            const float* __restrict__ src_b,
            const float* __restrict__ dst_w,
            const float* __restrict__ dst_b,
            const float* __restrict__ dec_w,
            const float* __restrict__ dec_b,
            float* __restrict__ out,
            int nrows)
{
    extern __shared__ float sm[];
    const int t = threadIdx.x;

    // ---- stage weights ----
    // w1 transpose: src w1[f][i] (f<64, i<128) -> s_w1t[i*64+f]
    for (int idx = t; idx < BDIM * H1DIM; idx += TPB) {
        int f = idx >> 7, i = idx & 127;
        sm[OFF_W1T + i * BDIM + f] = mlp_w1[idx];
    }
    for (int idx = t; idx < H1DIM * H2DIM; idx += TPB) sm[OFF_W2 + idx] = mlp_w2[idx];
    sm[OFF_B1 + t] = mlp_b1[t];
    if (t < 32) sm[OFF_B2 + t] = mlp_b2[t];
    for (int idx = t; idx < 256; idx += TPB) sm[OFF_ENCW + idx] = enc_w[idx];
    if (t < 32) sm[OFF_ENCB + t] = enc_b[t];
    if (t < 64) sm[OFF_SRCW + t] = src_w[t];
    if (t < 16) sm[OFF_SRCB + t] = src_b[t];
    if (t < 64) sm[OFF_DSTW + t] = dst_w[t];
    if (t < 16) sm[OFF_DSTB + t] = dst_b[t];
    for (int idx = t; idx < 192; idx += TPB) sm[OFF_DECW + idx] = dec_w[idx];
    if (t < 2) sm[OFF_DECB + t] = dec_b[t];
    if (t < 64) {
        sm[OFF_MEAN + t] = norm_mean[t];
        sm[OFF_ISTD + t] = 1.0f / (norm_std[t] + 1e-8f);
    }
    __syncthreads();

    const int row = blockIdx.x * TPB + t;
    if (row >= nrows) return;

    // ---- load x row (registers, as float2 pairs) ----
    float2 xr2[32];
    {
        const float4* xp = reinterpret_cast<const float4*>(x + (size_t)row * BDIM);
        #pragma unroll
        for (int q = 0; q < 16; q++) {
            float4 v = xp[q];
            xr2[2 * q]     = make_float2(v.x, v.y);
            xr2[2 * q + 1] = make_float2(v.z, v.w);
        }
    }

    // ---- per-group encoders on normalized x ----
    float henc[GRP * EDIM];   // h[g][e] at g*4+e
    #pragma unroll
    for (int g = 0; g < GRP; g++) {
        float xn[FPG];
        #pragma unroll
        for (int f = 0; f < FPG; f++) {
            int d = g * FPG + f;
            float xv = (d & 1) ? xr2[d >> 1].y : xr2[d >> 1].x;
            xn[f] = (xv - sm[OFF_MEAN + d]) * sm[OFF_ISTD + d];
        }
        #pragma unroll
        for (int e = 0; e < EDIM; e++) {
            float s = sm[OFF_ENCB + g * EDIM + e];
            #pragma unroll
            for (int f = 0; f < FPG; f++)
                s = fmaf(xn[f], sm[OFF_ENCW + (g * FPG + f) * EDIM + e], s);
            henc[g * EDIM + e] = fmaxf(s, 0.0f);
        }
    }

    // ---- fused MLP1 + MLP2 (streaming over i) ----
    float2 acc[16];   // x_hat pre-relu accumulators (32 values)
    #pragma unroll
    for (int j = 0; j < 16; j++)
        acc[j] = make_float2(sm[OFF_B2 + 2 * j], sm[OFF_B2 + 2 * j + 1]);

    #pragma unroll 1
    for (int i = 0; i < H1DIM; i++) {
        const float2* w1c = reinterpret_cast<const float2*>(sm + OFF_W1T + i * BDIM);
        float2 d0 = make_float2(0.f, 0.f), d1 = d0, d2 = d0, d3 = d0;
        #pragma unroll
        for (int f = 0; f < 32; f += 4) {
            d0 = ffma2(xr2[f],     w1c[f],     d0);
            d1 = ffma2(xr2[f + 1], w1c[f + 1], d1);
            d2 = ffma2(xr2[f + 2], w1c[f + 2], d2);
            d3 = ffma2(xr2[f + 3], w1c[f + 3], d3);
        }
        float s = ((d0.x + d0.y) + (d1.x + d1.y)) + ((d2.x + d2.y) + (d3.x + d3.y))
                  + sm[OFF_B1 + i];
        s = fmaxf(s, 0.0f);
        float2 sv = make_float2(s, s);
        const float2* w2r = reinterpret_cast<const float2*>(sm + OFF_W2 + i * H2DIM);
        #pragma unroll
        for (int j = 0; j < 16; j++) acc[j] = ffma2(sv, w2r[j], acc[j]);
    }

    // ---- decoder accumulator; fold x_hat (rows 0..31) and h (rows 32..63) ----
    const float2* decw2 = reinterpret_cast<const float2*>(sm + OFF_DECW);
    float2 o = make_float2(sm[OFF_DECB], sm[OFF_DECB + 1]);
    #pragma unroll
    for (int j = 0; j < 16; j++) {
        float xa = fmaxf(acc[j].x, 0.0f);
        float xb = fmaxf(acc[j].y, 0.0f);
        o = ffma2(make_float2(xa, xa), decw2[2 * j], o);
        o = ffma2(make_float2(xb, xb), decw2[2 * j + 1], o);
    }
    #pragma unroll
    for (int r = 0; r < 32; r++) {
        float hv = henc[r];
        o = ffma2(make_float2(hv, hv), decw2[32 + r], o);
    }

    // ---- GAT attention over the 8 group nodes (2 heads) ----
    const float inv_sqrt_a = 0.3535533905932738f;  // 1/sqrt(8)
    float att_out[GRP * EDIM];
    #pragma unroll
    for (int r = 0; r < GRP * EDIM; r++) att_out[r] = 0.0f;

    #pragma unroll
    for (int hd = 0; hd < HEADS; hd++) {
        float dstm[GRP][ADIM];
        #pragma unroll
        for (int k = 0; k < GRP; k++) {
            #pragma unroll
            for (int a = 0; a < ADIM; a++) {
                float s = sm[OFF_DSTB + hd * ADIM + a];
                #pragma unroll
                for (int e = 0; e < EDIM; e++)
                    s = fmaf(henc[k * EDIM + e], sm[OFF_DSTW + e * 16 + hd * ADIM + a], s);
                dstm[k][a] = s;
            }
        }
        #pragma unroll
        for (int g = 0; g < GRP; g++) {
            float srcg[ADIM];
            #pragma unroll
            for (int a = 0; a < ADIM; a++) {
                float s = sm[OFF_SRCB + hd * ADIM + a];
                #pragma unroll
                for (int e = 0; e < EDIM; e++)
                    s = fmaf(henc[g * EDIM + e], sm[OFF_SRCW + e * 16 + hd * ADIM + a], s);
                srcg[a] = s;
            }
            float sc[GRP];
            float mx = -3.402823466e+38f;
            #pragma unroll
            for (int k = 0; k < GRP; k++) {
                float s = 0.0f;
                #pragma unroll
                for (int a = 0; a < ADIM; a++) s = fmaf(srcg[a], dstm[k][a], s);
                sc[k] = s * inv_sqrt_a;
                mx = fmaxf(mx, sc[k]);
            }
            float sum = 0.0f;
            #pragma unroll
            for (int k = 0; k < GRP; k++) { sc[k] = __expf(sc[k] - mx); sum += sc[k]; }
            float inv = 1.0f / sum;
            #pragma unroll
            for (int k = 0; k < GRP; k++) {
                float w = sc[k] * inv;
                #pragma unroll
                for (int e = 0; e < EDIM; e++)
                    att_out[g * EDIM + e] = fmaf(w, henc[k * EDIM + e], att_out[g * EDIM + e]);
            }
        }
    }

    // ---- decoder: att_out rows 64..95, then store ----
    #pragma unroll
    for (int r = 0; r < 32; r++) {
        float av = att_out[r];
        o = ffma2(make_float2(av, av), decw2[64 + r], o);
    }
    reinterpret_cast<float2*>(out)[row] = o;
}

extern "C" void kernel_launch(void* const* d_in, const int* in_sizes, int n_in,
                              void* d_out, int out_size)
{
    const float* x         = (const float*)d_in[0];
    const float* norm_mean = (const float*)d_in[1];
    const float* norm_std  = (const float*)d_in[2];
    const float* mlp_w1    = (const float*)d_in[3];
    const float* mlp_b1    = (const float*)d_in[4];
    const float* mlp_w2    = (const float*)d_in[5];
    const float* mlp_b2    = (const float*)d_in[6];
    const float* enc_w     = (const float*)d_in[7];
    const float* enc_b     = (const float*)d_in[8];
    const float* src_w     = (const float*)d_in[9];
    const float* src_b     = (const float*)d_in[10];
    const float* dst_w     = (const float*)d_in[11];
    const float* dst_b     = (const float*)d_in[12];
    const float* dec_w     = (const float*)d_in[13];
    const float* dec_b     = (const float*)d_in[14];

    int nrows = in_sizes[0] / BDIM;
    int grid = (nrows + TPB - 1) / TPB;

    cudaFuncSetAttribute(ggan_kernel, cudaFuncAttributeMaxDynamicSharedMemorySize, SMEM_BYTES);
    ggan_kernel<<<grid, TPB, SMEM_BYTES>>>(x, norm_mean, norm_std,
                                           mlp_w1, mlp_b1, mlp_w2, mlp_b2,
                                           enc_w, enc_b, src_w, src_b, dst_w, dst_b,
                                           dec_w, dec_b,
                                           (float*)d_out, nrows);
}

// round 3
// speedup vs baseline: 2.7527x; 2.7527x over previous
#include <cuda_runtime.h>
#include <cstdint>

#define TPB 128

// ======================= SMEM layout (bytes) =======================
#define XS_STRIDE 68          // u32 per x row (padded)
#define W1_STRIDE 33          // u64 per w1 n-row (32 k-pairs + pad)
#define W2_STRIDE 65          // u64 per w2 n-row (64 k-pairs + pad)

#define OFF_XS   0            // 128*68*4      = 34816
#define OFF_W1   34816        // 128*33*8      = 33792
#define OFF_W2   68608        // 32*65*8       = 16640
#define OFF_B1   85248        // 128 fl
#define OFF_B2   85760        // 32 fl
#define OFF_ENCW 85888        // 256 fl (norm folded)
#define OFF_ENCB 86912        // 32 fl
#define OFF_ATTM 87040        // 32 fl
#define OFF_ATTV 87168        // 8 fl
#define OFF_DEC  87200        // 192 fl
#define OFF_DECB 87968        // 2 fl (+pad)
#define OFF_OP   87984        // 128 * float2 = 1024
#define SMEM_BYTES 89088

// ========================= helpers =========================
__device__ __forceinline__ uint32_t packbf2(float v0, float v1) {  // v0 -> low half
    uint32_t r;
    asm("cvt.rn.bf16x2.f32 %0, %1, %2;" : "=r"(r) : "f"(v1), "f"(v0));
    return r;
}
__device__ __forceinline__ float lowf(uint32_t p)  { return __uint_as_float(p << 16); }
__device__ __forceinline__ float highf(uint32_t p) { return __uint_as_float(p & 0xffff0000u); }

// hi pack + lo(residual) pack from a float2 (consecutive-k pair)
__device__ __forceinline__ void split2(float2 v, uint32_t& hi, uint32_t& lo) {
    hi = packbf2(v.x, v.y);
    lo = packbf2(v.x - lowf(hi), v.y - highf(hi));
}

__device__ __forceinline__ void mma16816(float* c, const uint32_t* a, uint32_t b0, uint32_t b1) {
    asm volatile(
        "mma.sync.aligned.m16n8k16.row.col.f32.bf16.bf16.f32 "
        "{%0,%1,%2,%3}, {%4,%5,%6,%7}, {%8,%9}, {%0,%1,%2,%3};"
        : "+f"(c[0]), "+f"(c[1]), "+f"(c[2]), "+f"(c[3])
        : "r"(a[0]), "r"(a[1]), "r"(a[2]), "r"(a[3]), "r"(b0), "r"(b1));
}

__device__ __forceinline__ float2 ffma2(float2 a, float2 b, float2 c) {
    float2 d;
    asm("fma.rn.f32x2 %0, %1, %2, %3;"
        : "=l"(reinterpret_cast<unsigned long long&>(d))
        : "l"(reinterpret_cast<unsigned long long&>(a)),
          "l"(reinterpret_cast<unsigned long long&>(b)),
          "l"(reinterpret_cast<unsigned long long&>(c)));
    return d;
}

__global__ void __launch_bounds__(TPB)
ggan_mma_kernel(const float* __restrict__ x,
                const float* __restrict__ norm_mean,
                const float* __restrict__ norm_std,
                const float* __restrict__ mlp_w1,
                const float* __restrict__ mlp_b1,
                const float* __restrict__ mlp_w2,
                const float* __restrict__ mlp_b2,
                const float* __restrict__ enc_w,
                const float* __restrict__ enc_b,
                const float* __restrict__ src_w,
                const float* __restrict__ src_b,
                const float* __restrict__ dst_w,
                const float* __restrict__ dst_b,
                const float* __restrict__ dec_w,
                const float* __restrict__ dec_b,
                float* __restrict__ out)
{
    extern __shared__ float smf[];
    char* smc = reinterpret_cast<char*>(smf);
    const int t = threadIdx.x;

    // ---------------- staging ----------------
    // x tile -> SMEM fp32 [row][k], stride XS_STRIDE (coalesced)
    {
        const float* xbase = x + (size_t)blockIdx.x * 128 * 64;
        #pragma unroll
        for (int i = 0; i < 16; i++) {
            int flat = i * 512 + t * 4;
            int row = flat >> 6, k = flat & 63;
            float4 v = *reinterpret_cast<const float4*>(xbase + flat);
            *reinterpret_cast<float4*>(smf + row * XS_STRIDE + k) = v;
        }
    }
    // w1: [k=64][n=128] gmem -> SMEM [n][kpair] u64 {hi2, lo2}
    {
        uint2* w1s = reinterpret_cast<uint2*>(smc + OFF_W1);
        #pragma unroll
        for (int kp = 0; kp < 32; kp++) {
            int n = t;
            float2 v = make_float2(mlp_w1[(2 * kp) * 128 + n], mlp_w1[(2 * kp + 1) * 128 + n]);
            uint32_t hi, lo; split2(v, hi, lo);
            w1s[n * W1_STRIDE + kp] = make_uint2(hi, lo);
        }
    }
    // w2: [k=128][n=32] gmem -> SMEM [n][kpair] u64 {hi2, lo2}
    {
        uint2* w2s = reinterpret_cast<uint2*>(smc + OFF_W2);
        #pragma unroll
        for (int i = 0; i < 16; i++) {
            int kp = i * 4 + (t >> 5);
            int n = t & 31;
            float2 v = make_float2(mlp_w2[(2 * kp) * 32 + n], mlp_w2[(2 * kp + 1) * 32 + n]);
            uint32_t hi, lo; split2(v, hi, lo);
            w2s[n * W2_STRIDE + kp] = make_uint2(hi, lo);
        }
    }
    smf[OFF_B1 / 4 + t] = mlp_b1[t];
    if (t < 32) smf[OFF_B2 / 4 + t] = mlp_b2[t];
    for (int idx = t; idx < 192; idx += TPB) smf[OFF_DEC / 4 + idx] = dec_w[idx];
    if (t < 2) smf[OFF_DECB / 4 + t] = dec_b[t];
    // encoder weights with normalization folded in
    for (int idx = t; idx < 256; idx += TPB) {
        int d = idx >> 2;
        smf[OFF_ENCW / 4 + idx] = enc_w[idx] / (norm_std[d] + 1e-8f);
    }
    if (t < 32) {
        int g = t >> 2, e = t & 3;
        float acc = enc_b[t];
        for (int f = 0; f < 8; f++) {
            int d = g * 8 + f;
            acc -= norm_mean[d] / (norm_std[d] + 1e-8f) * enc_w[d * 4 + e];
        }
        smf[OFF_ENCB / 4 + t] = acc;
    }
    // attention precompute: M = s*Sw*Dw^T, v2 = s*sb*Dw^T  (s = log2e/sqrt(8))
    {
        const float s = 0.3535533905932738f * 1.4426950408889634f;
        if (t < 32) {
            int h_ = t >> 4, rem = t & 15, e = rem >> 2, e2 = rem & 3;
            float acc = 0.0f;
            for (int a = 0; a < 8; a++)
                acc += src_w[e * 16 + h_ * 8 + a] * dst_w[e2 * 16 + h_ * 8 + a];
            smf[OFF_ATTM / 4 + h_ * 16 + e * 4 + e2] = acc * s;
        } else if (t < 40) {
            int t2 = t - 32, h_ = t2 >> 2, e2 = t2 & 3;
            float acc = 0.0f;
            for (int a = 0; a < 8; a++)
                acc += src_b[h_ * 8 + a] * dst_w[e2 * 16 + h_ * 8 + a];
            smf[OFF_ATTV / 4 + h_ * 4 + e2] = acc * s;
        }
    }
    __syncthreads();

    // ---------------- phase 1: scalar encoder + attention + partial decoder ----------------
    {
        float xrow[64];
        #pragma unroll
        for (int j = 0; j < 16; j++)
            reinterpret_cast<float4*>(xrow)[j] =
                reinterpret_cast<const float4*>(smf + t * XS_STRIDE)[j];

        float henc[32];
        #pragma unroll
        for (int g = 0; g < 8; g++) {
            #pragma unroll
            for (int e = 0; e < 4; e++) {
                float acc = smf[OFF_ENCB / 4 + g * 4 + e];
                #pragma unroll
                for (int f = 0; f < 8; f++)
                    acc = fmaf(xrow[g * 8 + f], smf[OFF_ENCW / 4 + (g * 8 + f) * 4 + e], acc);
                henc[g * 4 + e] = fmaxf(acc, 0.0f);
            }
        }

        float att[32];
        #pragma unroll
        for (int r = 0; r < 32; r++) att[r] = 0.0f;

        #pragma unroll
        for (int hd = 0; hd < 2; hd++) {
            const float* M  = smf + OFF_ATTM / 4 + hd * 16;
            const float* v2 = smf + OFF_ATTV / 4 + hd * 4;
            float tm[8][4], beta[8];
            #pragma unroll
            for (int k = 0; k < 8; k++) {
                #pragma unroll
                for (int e = 0; e < 4; e++) {
                    float acc = 0.0f;
                    #pragma unroll
                    for (int e2 = 0; e2 < 4; e2++)
                        acc = fmaf(M[e * 4 + e2], henc[k * 4 + e2], acc);
                    tm[k][e] = acc;
                }
                float b = 0.0f;
                #pragma unroll
                for (int e2 = 0; e2 < 4; e2++)
                    b = fmaf(v2[e2], henc[k * 4 + e2], b);
                beta[k] = b;
            }
            #pragma unroll
            for (int g = 0; g < 8; g++) {
                float sc[8];
                float mx = -3.402823466e+38f;
                #pragma unroll
                for (int k = 0; k < 8; k++) {
                    float s = beta[k];
                    #pragma unroll
                    for (int e = 0; e < 4; e++)
                        s = fmaf(henc[g * 4 + e], tm[k][e], s);
                    sc[k] = s;
                    mx = fmaxf(mx, s);
                }
                float sum = 0.0f;
                #pragma unroll
                for (int k = 0; k < 8; k++) { sc[k] = exp2f(sc[k] - mx); sum += sc[k]; }
                float inv = __fdividef(1.0f, sum);
                #pragma unroll
                for (int k = 0; k < 8; k++) {
                    float w = sc[k] * inv;
                    #pragma unroll
                    for (int e = 0; e < 4; e++)
                        att[g * 4 + e] = fmaf(w, henc[k * 4 + e], att[g * 4 + e]);
                }
            }
        }

        const float2* decw2 = reinterpret_cast<const float2*>(smf + OFF_DEC / 4);
        float2 op = make_float2(smf[OFF_DECB / 4], smf[OFF_DECB / 4 + 1]);
        #pragma unroll
        for (int r = 0; r < 32; r++)
            op = ffma2(make_float2(henc[r], henc[r]), decw2[32 + r], op);
        #pragma unroll
        for (int r = 0; r < 32; r++)
            op = ffma2(make_float2(att[r], att[r]), decw2[64 + r], op);
        reinterpret_cast<float2*>(smc + OFF_OP)[t] = op;
    }
    __syncwarp();

    // ---------------- phase 2: tensor MLP1 + MLP2 (per-warp, no barriers) ----------------
    const int lane = t & 31;
    const int lam = lane & 3;        // quad lane
    const int rq  = lane >> 2;       // quad row 0..7
    const int m0W = (t >> 5) * 32;   // warp's row base within CTA

    // A fragments of x (hi/lo bf16), m16n8k16 layout: [m-tile][k-tile][reg]
    uint32_t xah[2][4][4], xal[2][4][4];
    #pragma unroll
    for (int m = 0; m < 2; m++) {
        #pragma unroll
        for (int kt = 0; kt < 4; kt++) {
            int r0 = m0W + m * 16 + rq;
            int kb = kt * 16 + 2 * lam;
            float2 v0 = *reinterpret_cast<const float2*>(smf + r0 * XS_STRIDE + kb);
            float2 v1 = *reinterpret_cast<const float2*>(smf + (r0 + 8) * XS_STRIDE + kb);
            float2 v2 = *reinterpret_cast<const float2*>(smf + r0 * XS_STRIDE + kb + 8);
            float2 v3 = *reinterpret_cast<const float2*>(smf + (r0 + 8) * XS_STRIDE + kb + 8);
            split2(v0, xah[m][kt][0], xal[m][kt][0]);
            split2(v1, xah[m][kt][1], xal[m][kt][1]);
            split2(v2, xah[m][kt][2], xal[m][kt][2]);
            split2(v3, xah[m][kt][3], xal[m][kt][3]);
        }
    }

    const uint2* w1s = reinterpret_cast<const uint2*>(smc + OFF_W1);
    const uint2* w2s = reinterpret_cast<const uint2*>(smc + OFF_W2);

    float acc2[4][2][4];   // xhat accumulators [n2-tile][m-tile][c]
    #pragma unroll
    for (int n2 = 0; n2 < 4; n2++)
        #pragma unroll
        for (int m = 0; m < 2; m++)
            #pragma unroll
            for (int c = 0; c < 4; c++) acc2[n2][m][c] = 0.0f;

    #pragma unroll 1
    for (int p = 0; p < 8; p++) {
        // --- MLP1 for h1 columns [16p, 16p+16) : n-tiles {2p, 2p+1} ---
        float a1[2][2][4];
        #pragma unroll
        for (int nt = 0; nt < 2; nt++)
            #pragma unroll
            for (int m = 0; m < 2; m++)
                #pragma unroll
                for (int c = 0; c < 4; c++) a1[nt][m][c] = 0.0f;

        #pragma unroll
        for (int kt = 0; kt < 4; kt++) {
            #pragma unroll
            for (int nt = 0; nt < 2; nt++) {
                int n = p * 16 + nt * 8 + rq;
                uint2 u0 = w1s[n * W1_STRIDE + kt * 8 + lam];       // b0 (k pair)
                uint2 u1 = w1s[n * W1_STRIDE + kt * 8 + 4 + lam];   // b1 (k+8 pair)
                #pragma unroll
                for (int m = 0; m < 2; m++) {
                    mma16816(a1[nt][m], xah[m][kt], u0.x, u1.x);    // hi*hi
                    mma16816(a1[nt][m], xah[m][kt], u0.y, u1.y);    // hi*lo
                    mma16816(a1[nt][m], xal[m][kt], u0.x, u1.x);    // lo*hi
                }
            }
        }

        // --- bias + relu + pack -> A2 fragment (k-tile p of MLP2) ---
        float2 bb0 = *reinterpret_cast<const float2*>(smf + OFF_B1 / 4 + p * 16 + 2 * lam);
        float2 bb1 = *reinterpret_cast<const float2*>(smf + OFF_B1 / 4 + p * 16 + 8 + 2 * lam);
        uint32_t a2h[2][4], a2l[2][4];
        #pragma unroll
        for (int m = 0; m < 2; m++) {
            float2 h01 = make_float2(fmaxf(a1[0][m][0] + bb0.x, 0.0f),
                                     fmaxf(a1[0][m][1] + bb0.y, 0.0f));
            float2 h23 = make_float2(fmaxf(a1[0][m][2] + bb0.x, 0.0f),
                                     fmaxf(a1[0][m][3] + bb0.y, 0.0f));
            float2 h45 = make_float2(fmaxf(a1[1][m][0] + bb1.x, 0.0f),
                                     fmaxf(a1[1][m][1] + bb1.y, 0.0f));
            float2 h67 = make_float2(fmaxf(a1[1][m][2] + bb1.x, 0.0f),
                                     fmaxf(a1[1][m][3] + bb1.y, 0.0f));
            split2(h01, a2h[m][0], a2l[m][0]);
            split2(h23, a2h[m][1], a2l[m][1]);
            split2(h45, a2h[m][2], a2l[m][2]);
            split2(h67, a2h[m][3], a2l[m][3]);
        }

        // --- MLP2 k-step p ---
        #pragma unroll
        for (int n2 = 0; n2 < 4; n2++) {
            int n = n2 * 8 + rq;
            uint2 u0 = w2s[n * W2_STRIDE + p * 8 + lam];
            uint2 u1 = w2s[n * W2_STRIDE + p * 8 + 4 + lam];
            #pragma unroll
            for (int m = 0; m < 2; m++) {
                mma16816(acc2[n2][m], a2h[m], u0.x, u1.x);
                mma16816(acc2[n2][m], a2h[m], u0.y, u1.y);
                mma16816(acc2[n2][m], a2l[m], u0.x, u1.x);
            }
        }
    }

    // ---------------- epilogue: xhat = relu(acc2 + b2); o += xhat . dec ----------------
    float2 dv[4][2];
    float2 b2v[4];
    #pragma unroll
    for (int n2 = 0; n2 < 4; n2++) {
        float4 dq = *reinterpret_cast<const float4*>(smf + OFF_DEC / 4 + (n2 * 8 + 2 * lam) * 2);
        dv[n2][0] = make_float2(dq.x, dq.y);
        dv[n2][1] = make_float2(dq.z, dq.w);
        b2v[n2] = *reinterpret_cast<const float2*>(smf + OFF_B2 / 4 + n2 * 8 + 2 * lam);
    }

    const float2* opart = reinterpret_cast<const float2*>(smc + OFF_OP);
    #pragma unroll
    for (int m = 0; m < 2; m++) {
        #pragma unroll
        for (int h = 0; h < 2; h++) {
            float2 o = make_float2(0.0f, 0.0f);
            #pragma unroll
            for (int n2 = 0; n2 < 4; n2++) {
                float v0 = fmaxf(acc2[n2][m][2 * h]     + b2v[n2].x, 0.0f);
                float v1 = fmaxf(acc2[n2][m][2 * h + 1] + b2v[n2].y, 0.0f);
                o = ffma2(make_float2(v0, v0), dv[n2][0], o);
                o = ffma2(make_float2(v1, v1), dv[n2][1], o);
            }
            // reduce across the 4-lane quad
            o.x += __shfl_xor_sync(0xffffffffu, o.x, 1);
            o.y += __shfl_xor_sync(0xffffffffu, o.y, 1);
            o.x += __shfl_xor_sync(0xffffffffu, o.x, 2);
            o.y += __shfl_xor_sync(0xffffffffu, o.y, 2);
            if (lam == 0) {
                int rloc = m0W + m * 16 + h * 8 + rq;
                float2 op = opart[rloc];
                o.x += op.x; o.y += op.y;
                size_t grow = (size_t)blockIdx.x * 128 + rloc;
                reinterpret_cast<float2*>(out)[grow] = o;
            }
        }
    }
}

extern "C" void kernel_launch(void* const* d_in, const int* in_sizes, int n_in,
                              void* d_out, int out_size)
{
    const float* x         = (const float*)d_in[0];
    const float* norm_mean = (const float*)d_in[1];
    const float* norm_std  = (const float*)d_in[2];
    const float* mlp_w1    = (const float*)d_in[3];
    const float* mlp_b1    = (const float*)d_in[4];
    const float* mlp_w2    = (const float*)d_in[5];
    const float* mlp_b2    = (const float*)d_in[6];
    const float* enc_w     = (const float*)d_in[7];
    const float* enc_b     = (const float*)d_in[8];
    const float* src_w     = (const float*)d_in[9];
    const float* src_b     = (const float*)d_in[10];
    const float* dst_w     = (const float*)d_in[11];
    const float* dst_b     = (const float*)d_in[12];
    const float* dec_w     = (const float*)d_in[13];
    const float* dec_b     = (const float*)d_in[14];

    int nrows = in_sizes[0] / 64;
    int grid = nrows / 128;

    cudaFuncSetAttribute(ggan_mma_kernel, cudaFuncAttributeMaxDynamicSharedMemorySize, SMEM_BYTES);
    ggan_mma_kernel<<<grid, TPB, SMEM_BYTES>>>(x, norm_mean, norm_std,
                                               mlp_w1, mlp_b1, mlp_w2, mlp_b2,
                                               enc_w, enc_b, src_w, src_b, dst_w, dst_b,
                                               dec_w, dec_b, (float*)d_out);
}

// round 4
// speedup vs baseline: 2.9845x; 1.0842x over previous
#include <cuda_runtime.h>
#include <cstdint>

#define TPB 128

// ======================= SMEM layout (bytes) =======================
// w1: [n=128][j=0..15] uint4 {hi0,lo0,hi1,lo1}; j = kt*4+lam -> kpairs (kt*8+lam, kt*8+lam+4)
// w2: [n=32][j=0..31]  uint4; j = p*4+lam  -> kpairs (p*8+lam, p*8+lam+4)
// both XOR-swizzled: physical j = logical j ^ ((n&1)<<2)
#define OFF_W1   0        // 32768
#define OFF_W2   32768    // 16384
#define OFF_B1   49152    // 128 fl
#define OFF_B2   49664    // 32 fl
#define OFF_ENCW 49792    // 256 fl (norm folded)
#define OFF_ENCB 50816    // 32 fl
#define OFF_ATTM 50944    // 32 fl
#define OFF_ATTV 51072    // 8 fl
#define OFF_DEC  51104    // 192 fl
#define OFF_DECB 51872    // 2 fl
#define OFF_OP   51904    // 128 * float2 = 1024
#define SMEM_BYTES 52992

// ========================= helpers =========================
__device__ __forceinline__ uint32_t packbf2(float v0, float v1) {  // v0 -> low half
    uint32_t r;
    asm("cvt.rn.bf16x2.f32 %0, %1, %2;" : "=r"(r) : "f"(v1), "f"(v0));
    return r;
}
__device__ __forceinline__ float lowf(uint32_t p)  { return __uint_as_float(p << 16); }
__device__ __forceinline__ float highf(uint32_t p) { return __uint_as_float(p & 0xffff0000u); }

__device__ __forceinline__ void split2(float2 v, uint32_t& hi, uint32_t& lo) {
    hi = packbf2(v.x, v.y);
    lo = packbf2(v.x - lowf(hi), v.y - highf(hi));
}

__device__ __forceinline__ void mma16816(float* c, const uint32_t* a, uint32_t b0, uint32_t b1) {
    asm volatile(
        "mma.sync.aligned.m16n8k16.row.col.f32.bf16.bf16.f32 "
        "{%0,%1,%2,%3}, {%4,%5,%6,%7}, {%8,%9}, {%0,%1,%2,%3};"
        : "+f"(c[0]), "+f"(c[1]), "+f"(c[2]), "+f"(c[3])
        : "r"(a[0]), "r"(a[1]), "r"(a[2]), "r"(a[3]), "r"(b0), "r"(b1));
}

__device__ __forceinline__ float2 ffma2(float2 a, float2 b, float2 c) {
    float2 d;
    asm("fma.rn.f32x2 %0, %1, %2, %3;"
        : "=l"(reinterpret_cast<unsigned long long&>(d))
        : "l"(reinterpret_cast<unsigned long long&>(a)),
          "l"(reinterpret_cast<unsigned long long&>(b)),
          "l"(reinterpret_cast<unsigned long long&>(c)));
    return d;
}

__global__ void __launch_bounds__(TPB, 3)
ggan_mma_kernel(const float* __restrict__ x,
                const float* __restrict__ norm_mean,
                const float* __restrict__ norm_std,
                const float* __restrict__ mlp_w1,
                const float* __restrict__ mlp_b1,
                const float* __restrict__ mlp_w2,
                const float* __restrict__ mlp_b2,
                const float* __restrict__ enc_w,
                const float* __restrict__ enc_b,
                const float* __restrict__ src_w,
                const float* __restrict__ src_b,
                const float* __restrict__ dst_w,
                const float* __restrict__ dst_b,
                const float* __restrict__ dec_w,
                const float* __restrict__ dec_b,
                float* __restrict__ out)
{
    extern __shared__ float smf[];
    char* smc = reinterpret_cast<char*>(smf);
    const int t = threadIdx.x;
    const size_t rowbase = (size_t)blockIdx.x * 128;
    const float* __restrict__ xg = x + rowbase * 64;

    // ---------------- staging ----------------
    {   // w1: [k=64][n=128] gmem -> [n][j] uint4
        uint4* w1s = reinterpret_cast<uint4*>(smc + OFF_W1);
        const int n = t;
        #pragma unroll
        for (int j = 0; j < 16; j++) {
            int k0 = ((j >> 2) * 8 + (j & 3)) * 2;
            float2 v0 = make_float2(mlp_w1[k0 * 128 + n],       mlp_w1[(k0 + 1) * 128 + n]);
            float2 v1 = make_float2(mlp_w1[(k0 + 8) * 128 + n], mlp_w1[(k0 + 9) * 128 + n]);
            uint32_t h0, l0, h1, l1;
            split2(v0, h0, l0); split2(v1, h1, l1);
            w1s[n * 16 + (j ^ ((n & 1) << 2))] = make_uint4(h0, l0, h1, l1);
        }
    }
    {   // w2: [k=128][n=32] gmem -> [n][j=0..31] uint4 ; 1024 uint4, 8 per thread
        uint4* w2s = reinterpret_cast<uint4*>(smc + OFF_W2);
        const int n = t & 31;
        #pragma unroll
        for (int jj = 0; jj < 8; jj++) {
            int j = (t >> 5) * 8 + jj;            // 0..31
            int k0 = ((j >> 2) * 8 + (j & 3)) * 2;
            float2 v0 = make_float2(mlp_w2[k0 * 32 + n],       mlp_w2[(k0 + 1) * 32 + n]);
            float2 v1 = make_float2(mlp_w2[(k0 + 8) * 32 + n], mlp_w2[(k0 + 9) * 32 + n]);
            uint32_t h0, l0, h1, l1;
            split2(v0, h0, l0); split2(v1, h1, l1);
            w2s[n * 32 + (j ^ ((n & 1) << 2))] = make_uint4(h0, l0, h1, l1);
        }
    }
    smf[OFF_B1 / 4 + t] = mlp_b1[t];
    if (t < 32) smf[OFF_B2 / 4 + t] = mlp_b2[t];
    for (int idx = t; idx < 192; idx += TPB) smf[OFF_DEC / 4 + idx] = dec_w[idx];
    if (t < 2) smf[OFF_DECB / 4 + t] = dec_b[t];
    for (int idx = t; idx < 256; idx += TPB) {
        int d = idx >> 2;
        smf[OFF_ENCW / 4 + idx] = enc_w[idx] / (norm_std[d] + 1e-8f);
    }
    if (t < 32) {
        int g = t >> 2, e = t & 3;
        float acc = enc_b[t];
        for (int f = 0; f < 8; f++) {
            int d = g * 8 + f;
            acc -= norm_mean[d] / (norm_std[d] + 1e-8f) * enc_w[d * 4 + e];
        }
        smf[OFF_ENCB / 4 + t] = acc;
    }
    {   // attention precompute: M = s*Sw*Dw^T, v2 = s*sb*Dw^T  (s = log2e/sqrt(8))
        const float s = 0.3535533905932738f * 1.4426950408889634f;
        if (t < 32) {
            int h_ = t >> 4, rem = t & 15, e = rem >> 2, e2 = rem & 3;
            float acc = 0.0f;
            for (int a = 0; a < 8; a++)
                acc += src_w[e * 16 + h_ * 8 + a] * dst_w[e2 * 16 + h_ * 8 + a];
            smf[OFF_ATTM / 4 + h_ * 16 + e * 4 + e2] = acc * s;
        } else if (t < 40) {
            int t2 = t - 32, h_ = t2 >> 2, e2 = t2 & 3;
            float acc = 0.0f;
            for (int a = 0; a < 8; a++)
                acc += src_b[h_ * 8 + a] * dst_w[e2 * 16 + h_ * 8 + a];
            smf[OFF_ATTV / 4 + h_ * 4 + e2] = acc * s;
        }
    }
    __syncthreads();

    // ---------------- phase 1: encoder + attention + partial decoder ----------------
    {
        float xrow[64];
        const float4* xp = reinterpret_cast<const float4*>(xg + t * 64);
        #pragma unroll
        for (int j = 0; j < 16; j++) reinterpret_cast<float4*>(xrow)[j] = xp[j];

        float henc[32];
        const float4* encw4 = reinterpret_cast<const float4*>(smf + OFF_ENCW / 4);
        const float4* encb4 = reinterpret_cast<const float4*>(smf + OFF_ENCB / 4);
        #pragma unroll
        for (int g = 0; g < 8; g++) {
            float4 b = encb4[g];
            float2 h01 = make_float2(b.x, b.y);
            float2 h23 = make_float2(b.z, b.w);
            #pragma unroll
            for (int f = 0; f < 8; f++) {
                float xv = xrow[g * 8 + f];
                float4 w = encw4[g * 8 + f];
                h01 = ffma2(make_float2(xv, xv), make_float2(w.x, w.y), h01);
                h23 = ffma2(make_float2(xv, xv), make_float2(w.z, w.w), h23);
            }
            henc[g * 4 + 0] = fmaxf(h01.x, 0.0f);
            henc[g * 4 + 1] = fmaxf(h01.y, 0.0f);
            henc[g * 4 + 2] = fmaxf(h23.x, 0.0f);
            henc[g * 4 + 3] = fmaxf(h23.y, 0.0f);
        }

        float att[32];
        #pragma unroll
        for (int r = 0; r < 32; r++) att[r] = 0.0f;

        #pragma unroll
        for (int hd = 0; hd < 2; hd++) {
            const float* M  = smf + OFF_ATTM / 4 + hd * 16;
            const float* v2 = smf + OFF_ATTV / 4 + hd * 4;
            float tm[8][4], beta[8];
            #pragma unroll
            for (int k = 0; k < 8; k++) {
                #pragma unroll
                for (int e = 0; e < 4; e++) {
                    float acc = 0.0f;
                    #pragma unroll
                    for (int e2 = 0; e2 < 4; e2++)
                        acc = fmaf(M[e * 4 + e2], henc[k * 4 + e2], acc);
                    tm[k][e] = acc;
                }
                float b = 0.0f;
                #pragma unroll
                for (int e2 = 0; e2 < 4; e2++)
                    b = fmaf(v2[e2], henc[k * 4 + e2], b);
                beta[k] = b;
            }
            #pragma unroll
            for (int g = 0; g < 8; g++) {
                float sc[8];
                float mx = -3.402823466e+38f;
                #pragma unroll
                for (int k = 0; k < 8; k++) {
                    float s = beta[k];
                    #pragma unroll
                    for (int e = 0; e < 4; e++)
                        s = fmaf(henc[g * 4 + e], tm[k][e], s);
                    sc[k] = s;
                    mx = fmaxf(mx, s);
                }
                float sum = 0.0f;
                #pragma unroll
                for (int k = 0; k < 8; k++) { sc[k] = exp2f(sc[k] - mx); sum += sc[k]; }
                float inv = __fdividef(1.0f, sum);
                #pragma unroll
                for (int k = 0; k < 8; k++) {
                    float w = sc[k] * inv;
                    #pragma unroll
                    for (int e = 0; e < 4; e++)
                        att[g * 4 + e] = fmaf(w, henc[k * 4 + e], att[g * 4 + e]);
                }
            }
        }

        const float2* decw2 = reinterpret_cast<const float2*>(smf + OFF_DEC / 4);
        float2 op = make_float2(smf[OFF_DECB / 4], smf[OFF_DECB / 4 + 1]);
        #pragma unroll
        for (int r = 0; r < 32; r++)
            op = ffma2(make_float2(henc[r], henc[r]), decw2[32 + r], op);
        #pragma unroll
        for (int r = 0; r < 32; r++)
            op = ffma2(make_float2(att[r], att[r]), decw2[64 + r], op);
        reinterpret_cast<float2*>(smc + OFF_OP)[t] = op;
    }
    __syncwarp();

    // ---------------- phase 2: tensor MLP1 + MLP2 ----------------
    const int lane = t & 31;
    const int lam = lane & 3;
    const int rq  = lane >> 2;
    const int m0W = (t >> 5) * 32;
    const int swz = (rq & 1) << 2;     // XOR swizzle (n&1 == rq&1 for all weight rows used)

    uint32_t xah[2][4][4], xal[2][4][4];
    #pragma unroll
    for (int m = 0; m < 2; m++) {
        #pragma unroll
        for (int kt = 0; kt < 4; kt++) {
            int r0 = m0W + m * 16 + rq;
            int kb = kt * 16 + 2 * lam;
            float2 v0 = *reinterpret_cast<const float2*>(xg + r0 * 64 + kb);
            float2 v1 = *reinterpret_cast<const float2*>(xg + (r0 + 8) * 64 + kb);
            float2 v2 = *reinterpret_cast<const float2*>(xg + r0 * 64 + kb + 8);
            float2 v3 = *reinterpret_cast<const float2*>(xg + (r0 + 8) * 64 + kb + 8);
            split2(v0, xah[m][kt][0], xal[m][kt][0]);
            split2(v1, xah[m][kt][1], xal[m][kt][1]);
            split2(v2, xah[m][kt][2], xal[m][kt][2]);
            split2(v3, xah[m][kt][3], xal[m][kt][3]);
        }
    }

    const uint4* w1s = reinterpret_cast<const uint4*>(smc + OFF_W1);
    const uint4* w2s = reinterpret_cast<const uint4*>(smc + OFF_W2);

    float acc2[4][2][4];
    #pragma unroll
    for (int n2 = 0; n2 < 4; n2++)
        #pragma unroll
        for (int m = 0; m < 2; m++)
            #pragma unroll
            for (int c = 0; c < 4; c++) acc2[n2][m][c] = 0.0f;

    #pragma unroll 1
    for (int p = 0; p < 8; p++) {
        float a1[2][2][4];
        #pragma unroll
        for (int nt = 0; nt < 2; nt++)
            #pragma unroll
            for (int m = 0; m < 2; m++)
                #pragma unroll
                for (int c = 0; c < 4; c++) a1[nt][m][c] = 0.0f;

        #pragma unroll
        for (int kt = 0; kt < 4; kt++) {
            #pragma unroll
            for (int nt = 0; nt < 2; nt++) {
                int n = p * 16 + nt * 8 + rq;
                uint4 u = w1s[n * 16 + ((kt * 4 + lam) ^ swz)];
                #pragma unroll
                for (int m = 0; m < 2; m++) {
                    mma16816(a1[nt][m], xah[m][kt], u.x, u.z);    // hi*hi
                    mma16816(a1[nt][m], xah[m][kt], u.y, u.w);    // hi*lo
                    mma16816(a1[nt][m], xal[m][kt], u.x, u.z);    // lo*hi
                }
            }
        }

        float2 bb0 = *reinterpret_cast<const float2*>(smf + OFF_B1 / 4 + p * 16 + 2 * lam);
        float2 bb1 = *reinterpret_cast<const float2*>(smf + OFF_B1 / 4 + p * 16 + 8 + 2 * lam);
        uint32_t a2h[2][4], a2l[2][4];
        #pragma unroll
        for (int m = 0; m < 2; m++) {
            float2 h01 = make_float2(fmaxf(a1[0][m][0] + bb0.x, 0.0f),
                                     fmaxf(a1[0][m][1] + bb0.y, 0.0f));
            float2 h23 = make_float2(fmaxf(a1[0][m][2] + bb0.x, 0.0f),
                                     fmaxf(a1[0][m][3] + bb0.y, 0.0f));
            float2 h45 = make_float2(fmaxf(a1[1][m][0] + bb1.x, 0.0f),
                                     fmaxf(a1[1][m][1] + bb1.y, 0.0f));
            float2 h67 = make_float2(fmaxf(a1[1][m][2] + bb1.x, 0.0f),
                                     fmaxf(a1[1][m][3] + bb1.y, 0.0f));
            split2(h01, a2h[m][0], a2l[m][0]);
            split2(h23, a2h[m][1], a2l[m][1]);
            split2(h45, a2h[m][2], a2l[m][2]);
            split2(h67, a2h[m][3], a2l[m][3]);
        }

        #pragma unroll
        for (int n2 = 0; n2 < 4; n2++) {
            int n = n2 * 8 + rq;
            uint4 u = w2s[n * 32 + ((p * 4 + lam) ^ swz)];
            #pragma unroll
            for (int m = 0; m < 2; m++) {
                mma16816(acc2[n2][m], a2h[m], u.x, u.z);
                mma16816(acc2[n2][m], a2h[m], u.y, u.w);
                mma16816(acc2[n2][m], a2l[m], u.x, u.z);
            }
        }
    }

    // ---------------- epilogue ----------------
    float2 dv[4][2];
    float2 b2v[4];
    #pragma unroll
    for (int n2 = 0; n2 < 4; n2++) {
        float4 dq = *reinterpret_cast<const float4*>(smf + OFF_DEC / 4 + (n2 * 8 + 2 * lam) * 2);
        dv[n2][0] = make_float2(dq.x, dq.y);
        dv[n2][1] = make_float2(dq.z, dq.w);
        b2v[n2] = *reinterpret_cast<const float2*>(smf + OFF_B2 / 4 + n2 * 8 + 2 * lam);
    }

    __syncwarp();
    const float2* opart = reinterpret_cast<const float2*>(smc + OFF_OP);
    #pragma unroll
    for (int m = 0; m < 2; m++) {
        #pragma unroll
        for (int h = 0; h < 2; h++) {
            float2 o = make_float2(0.0f, 0.0f);
            #pragma unroll
            for (int n2 = 0; n2 < 4; n2++) {
                float v0 = fmaxf(acc2[n2][m][2 * h]     + b2v[n2].x, 0.0f);
                float v1 = fmaxf(acc2[n2][m][2 * h + 1] + b2v[n2].y, 0.0f);
                o = ffma2(make_float2(v0, v0), dv[n2][0], o);
                o = ffma2(make_float2(v1, v1), dv[n2][1], o);
            }
            o.x += __shfl_xor_sync(0xffffffffu, o.x, 1);
            o.y += __shfl_xor_sync(0xffffffffu, o.y, 1);
            o.x += __shfl_xor_sync(0xffffffffu, o.x, 2);
            o.y += __shfl_xor_sync(0xffffffffu, o.y, 2);
            if (lam == 0) {
                int rloc = m0W + m * 16 + h * 8 + rq;
                float2 op = opart[rloc];
                o.x += op.x; o.y += op.y;
                reinterpret_cast<float2*>(out)[rowbase + rloc] = o;
            }
        }
    }
}

extern "C" void kernel_launch(void* const* d_in, const int* in_sizes, int n_in,
                              void* d_out, int out_size)
{
    const float* x         = (const float*)d_in[0];
    const float* norm_mean = (const float*)d_in[1];
    const float* norm_std  = (const float*)d_in[2];
    const float* mlp_w1    = (const float*)d_in[3];
    const float* mlp_b1    = (const float*)d_in[4];
    const float* mlp_w2    = (const float*)d_in[5];
    const float* mlp_b2    = (const float*)d_in[6];
    const float* enc_w     = (const float*)d_in[7];
    const float* enc_b     = (const float*)d_in[8];
    const float* src_w     = (const float*)d_in[9];
    const float* src_b     = (const float*)d_in[10];
    const float* dst_w     = (const float*)d_in[11];
    const float* dst_b     = (const float*)d_in[12];
    const float* dec_w     = (const float*)d_in[13];
    const float* dec_b     = (const float*)d_in[14];

    int nrows = in_sizes[0] / 64;
    int grid = nrows / 128;

    cudaFuncSetAttribute(ggan_mma_kernel, cudaFuncAttributeMaxDynamicSharedMemorySize, SMEM_BYTES);
    ggan_mma_kernel<<<grid, TPB, SMEM_BYTES>>>(x, norm_mean, norm_std,
                                               mlp_w1, mlp_b1, mlp_w2, mlp_b2,
                                               enc_w, enc_b, src_w, src_b, dst_w, dst_b,
                                               dec_w, dec_b, (float*)d_out);
}

// round 5
// speedup vs baseline: 3.7734x; 1.2644x over previous
#include <cuda_runtime.h>
#include <cstdint>

#define TPB 128

// ======================= SMEM layout (bytes) =======================
// w1: [n=128][j=0..15] uint2 {b0,b1} fp16 ; j = kt*4+lam -> kpairs (kt*8+lam, kt*8+lam+4)
// w2: [n=32][j=0..31]  uint2 ; j = p*4+lam -> kpairs (p*8+lam, p*8+lam+4)
// XOR swizzle: physical j = logical j ^ ((n&3)<<2)
#define OFF_W1   0        // 16384
#define OFF_W2   16384    // 8192
#define OFF_B1   24576    // 128 fl
#define OFF_B2   25088    // 32 fl
#define OFF_ENCW 25216    // 256 fl (norm folded)
#define OFF_ENCB 26240    // 32 fl
#define OFF_ATTM 26368    // 32 fl : [h][e2][e] (scaled)
#define OFF_ATTV 26496    // 8 fl  : [h][e2]
#define OFF_DEC  26528    // 192 fl
#define OFF_DECB 27296    // 2 fl
#define OFF_OP   27304    // 128 * float2 = 1024
#define SMEM_BYTES 28416

// ========================= helpers =========================
__device__ __forceinline__ uint32_t packh2(float2 v) {   // v.x -> low half
    uint32_t r;
    asm("cvt.rn.f16x2.f32 %0, %1, %2;" : "=r"(r) : "f"(v.y), "f"(v.x));
    return r;
}
__device__ __forceinline__ float2 unpackh2(uint32_t u) {
    float a, b;
    asm("{.reg .b16 l,h;\n\t mov.b32 {l,h}, %2;\n\t cvt.f32.f16 %0, l;\n\t cvt.f32.f16 %1, h;}"
        : "=f"(a), "=f"(b) : "r"(u));
    return make_float2(a, b);
}
// fp16 hi + fp16 residual split of an fp32 pair
__device__ __forceinline__ void split2h(float2 v, uint32_t& hi, uint32_t& lo) {
    hi = packh2(v);
    float2 b = unpackh2(hi);
    lo = packh2(make_float2(v.x - b.x, v.y - b.y));
}

__device__ __forceinline__ void mma16816(float* c, const uint32_t* a, uint32_t b0, uint32_t b1) {
    asm volatile(
        "mma.sync.aligned.m16n8k16.row.col.f32.f16.f16.f32 "
        "{%0,%1,%2,%3}, {%4,%5,%6,%7}, {%8,%9}, {%0,%1,%2,%3};"
        : "+f"(c[0]), "+f"(c[1]), "+f"(c[2]), "+f"(c[3])
        : "r"(a[0]), "r"(a[1]), "r"(a[2]), "r"(a[3]), "r"(b0), "r"(b1));
}

__device__ __forceinline__ float2 ffma2(float2 a, float2 b, float2 c) {
    float2 d;
    asm("fma.rn.f32x2 %0, %1, %2, %3;"
        : "=l"(reinterpret_cast<unsigned long long&>(d))
        : "l"(reinterpret_cast<unsigned long long&>(a)),
          "l"(reinterpret_cast<unsigned long long&>(b)),
          "l"(reinterpret_cast<unsigned long long&>(c)));
    return d;
}

__global__ void __launch_bounds__(TPB, 3)
ggan_mma_kernel(const float* __restrict__ x,
                const float* __restrict__ norm_mean,
                const float* __restrict__ norm_std,
                const float* __restrict__ mlp_w1,
                const float* __restrict__ mlp_b1,
                const float* __restrict__ mlp_w2,
                const float* __restrict__ mlp_b2,
                const float* __restrict__ enc_w,
                const float* __restrict__ enc_b,
                const float* __restrict__ src_w,
                const float* __restrict__ src_b,
                const float* __restrict__ dst_w,
                const float* __restrict__ dst_b,
                const float* __restrict__ dec_w,
                const float* __restrict__ dec_b,
                float* __restrict__ out)
{
    extern __shared__ float smf[];
    char* smc = reinterpret_cast<char*>(smf);
    const int t = threadIdx.x;
    const size_t rowbase = (size_t)blockIdx.x * 128;
    const float* __restrict__ xg = x + rowbase * 64;

    // ---------------- staging ----------------
    {   // w1: [k=64][n=128] gmem -> [n][j] uint2 (single fp16)
        uint2* w1s = reinterpret_cast<uint2*>(smc + OFF_W1);
        const int n = t;
        #pragma unroll
        for (int j = 0; j < 16; j++) {
            int k0 = ((j >> 2) * 8 + (j & 3)) * 2;
            uint32_t b0 = packh2(make_float2(mlp_w1[k0 * 128 + n],       mlp_w1[(k0 + 1) * 128 + n]));
            uint32_t b1 = packh2(make_float2(mlp_w1[(k0 + 8) * 128 + n], mlp_w1[(k0 + 9) * 128 + n]));
            w1s[n * 16 + (j ^ ((n & 3) << 2))] = make_uint2(b0, b1);
        }
    }
    {   // w2: [k=128][n=32] gmem -> [n][j=0..31] uint2
        uint2* w2s = reinterpret_cast<uint2*>(smc + OFF_W2);
        const int n = t & 31;
        #pragma unroll
        for (int jj = 0; jj < 8; jj++) {
            int j = (t >> 5) * 8 + jj;            // 0..31
            int k0 = ((j >> 2) * 8 + (j & 3)) * 2;
            uint32_t b0 = packh2(make_float2(mlp_w2[k0 * 32 + n],       mlp_w2[(k0 + 1) * 32 + n]));
            uint32_t b1 = packh2(make_float2(mlp_w2[(k0 + 8) * 32 + n], mlp_w2[(k0 + 9) * 32 + n]));
            w2s[n * 32 + (j ^ ((n & 3) << 2))] = make_uint2(b0, b1);
        }
    }
    smf[OFF_B1 / 4 + t] = mlp_b1[t];
    if (t < 32) smf[OFF_B2 / 4 + t] = mlp_b2[t];
    for (int idx = t; idx < 192; idx += TPB) smf[OFF_DEC / 4 + idx] = dec_w[idx];
    if (t < 2) smf[OFF_DECB / 4 + t] = dec_b[t];
    for (int idx = t; idx < 256; idx += TPB) {
        int d = idx >> 2;
        smf[OFF_ENCW / 4 + idx] = enc_w[idx] / (norm_std[d] + 1e-8f);
    }
    if (t < 32) {
        int g = t >> 2, e = t & 3;
        float acc = enc_b[t];
        for (int f = 0; f < 8; f++) {
            int d = g * 8 + f;
            acc -= norm_mean[d] / (norm_std[d] + 1e-8f) * enc_w[d * 4 + e];
        }
        smf[OFF_ENCB / 4 + t] = acc;
    }
    {   // attention precompute: M'[h][e2][e] = s*sum_a Sw[e][ha]*Dw[e2][ha];  v2[h][e2]
        const float s = 0.3535533905932738f * 1.4426950408889634f;   // log2e/sqrt(8)
        if (t < 32) {
            int h_ = t >> 4, rem = t & 15, e2 = rem >> 2, e = rem & 3;
            float acc = 0.0f;
            for (int a = 0; a < 8; a++)
                acc += src_w[e * 16 + h_ * 8 + a] * dst_w[e2 * 16 + h_ * 8 + a];
            smf[OFF_ATTM / 4 + h_ * 16 + e2 * 4 + e] = acc * s;
        } else if (t < 40) {
            int t2 = t - 32, h_ = t2 >> 2, e2 = t2 & 3;
            float acc = 0.0f;
            for (int a = 0; a < 8; a++)
                acc += src_b[h_ * 8 + a] * dst_w[e2 * 16 + h_ * 8 + a];
            smf[OFF_ATTV / 4 + h_ * 4 + e2] = acc * s;
        }
    }
    __syncthreads();

    // ---------------- phase 1: encoder + attention + partial decoder ----------------
    {
        float xrow[64];
        const float4* xp = reinterpret_cast<const float4*>(xg + t * 64);
        #pragma unroll
        for (int j = 0; j < 16; j++) reinterpret_cast<float4*>(xrow)[j] = xp[j];

        float2 henc2[16];         // [g][half] : (h[g][0..1]), (h[g][2..3])
        const float4* encw4 = reinterpret_cast<const float4*>(smf + OFF_ENCW / 4);
        const float4* encb4 = reinterpret_cast<const float4*>(smf + OFF_ENCB / 4);
        #pragma unroll
        for (int g = 0; g < 8; g++) {
            float4 b = encb4[g];
            float2 h01 = make_float2(b.x, b.y);
            float2 h23 = make_float2(b.z, b.w);
            #pragma unroll
            for (int f = 0; f < 8; f++) {
                float xv = xrow[g * 8 + f];
                float4 w = encw4[g * 8 + f];
                h01 = ffma2(make_float2(xv, xv), make_float2(w.x, w.y), h01);
                h23 = ffma2(make_float2(xv, xv), make_float2(w.z, w.w), h23);
            }
            henc2[g * 2]     = make_float2(fmaxf(h01.x, 0.0f), fmaxf(h01.y, 0.0f));
            henc2[g * 2 + 1] = make_float2(fmaxf(h23.x, 0.0f), fmaxf(h23.y, 0.0f));
        }

        float2 att2[16];
        #pragma unroll
        for (int r = 0; r < 16; r++) att2[r] = make_float2(0.0f, 0.0f);

        #pragma unroll
        for (int hd = 0; hd < 2; hd++) {
            const float2* M2 = reinterpret_cast<const float2*>(smf + OFF_ATTM / 4 + hd * 16);  // [e2][j]
            const float* v2  = smf + OFF_ATTV / 4 + hd * 4;
            float2 tm2[8][2];
            float beta[8];
            #pragma unroll
            for (int k = 0; k < 8; k++) {
                float2 t0 = make_float2(0.0f, 0.0f), t1 = t0;
                float b = 0.0f;
                #pragma unroll
                for (int e2 = 0; e2 < 4; e2++) {
                    float hv = (e2 & 1) ? henc2[k * 2 + (e2 >> 1)].y : henc2[k * 2 + (e2 >> 1)].x;
                    float2 hb = make_float2(hv, hv);
                    t0 = ffma2(hb, M2[e2 * 2], t0);
                    t1 = ffma2(hb, M2[e2 * 2 + 1], t1);
                    b = fmaf(hv, v2[e2], b);
                }
                tm2[k][0] = t0; tm2[k][1] = t1; beta[k] = b;
            }
            #pragma unroll
            for (int g = 0; g < 8; g++) {
                float2 hg0 = henc2[g * 2], hg1 = henc2[g * 2 + 1];
                float sc[8];
                float mx = -3.402823466e+38f;
                #pragma unroll
                for (int k = 0; k < 8; k++) {
                    float2 d = ffma2(hg0, tm2[k][0],
                              ffma2(hg1, tm2[k][1], make_float2(0.0f, 0.0f)));
                    float s = beta[k] + d.x + d.y;
                    sc[k] = s;
                    mx = fmaxf(mx, s);
                }
                float sum = 0.0f;
                #pragma unroll
                for (int k = 0; k < 8; k++) { sc[k] = exp2f(sc[k] - mx); sum += sc[k]; }
                float inv = __fdividef(1.0f, sum);
                #pragma unroll
                for (int k = 0; k < 8; k++) {
                    float w = sc[k] * inv;
                    float2 wb = make_float2(w, w);
                    att2[g * 2]     = ffma2(wb, henc2[k * 2],     att2[g * 2]);
                    att2[g * 2 + 1] = ffma2(wb, henc2[k * 2 + 1], att2[g * 2 + 1]);
                }
            }
        }

        const float2* decw2 = reinterpret_cast<const float2*>(smf + OFF_DEC / 4);
        float2 op = make_float2(smf[OFF_DECB / 4], smf[OFF_DECB / 4 + 1]);
        #pragma unroll
        for (int j = 0; j < 16; j++) {
            float2 hv = henc2[j];
            op = ffma2(make_float2(hv.x, hv.x), decw2[32 + 2 * j], op);
            op = ffma2(make_float2(hv.y, hv.y), decw2[32 + 2 * j + 1], op);
        }
        #pragma unroll
        for (int j = 0; j < 16; j++) {
            float2 av = att2[j];
            op = ffma2(make_float2(av.x, av.x), decw2[64 + 2 * j], op);
            op = ffma2(make_float2(av.y, av.y), decw2[64 + 2 * j + 1], op);
        }
        reinterpret_cast<float2*>(smc + OFF_OP)[t] = op;
    }
    __syncwarp();

    // ---------------- phase 2: tensor MLP1 + MLP2 (fp16, A-split 2-term) ----------------
    const int lane = t & 31;
    const int lam = lane & 3;
    const int rq  = lane >> 2;
    const int m0W = (t >> 5) * 32;
    const int swz = (rq & 3) << 2;     // XOR swizzle: matches (n&3) of every weight row read

    uint32_t xah[2][4][4], xal[2][4][4];
    #pragma unroll
    for (int m = 0; m < 2; m++) {
        #pragma unroll
        for (int kt = 0; kt < 4; kt++) {
            int r0 = m0W + m * 16 + rq;
            int kb = kt * 16 + 2 * lam;
            float2 v0 = *reinterpret_cast<const float2*>(xg + r0 * 64 + kb);
            float2 v1 = *reinterpret_cast<const float2*>(xg + (r0 + 8) * 64 + kb);
            float2 v2 = *reinterpret_cast<const float2*>(xg + r0 * 64 + kb + 8);
            float2 v3 = *reinterpret_cast<const float2*>(xg + (r0 + 8) * 64 + kb + 8);
            split2h(v0, xah[m][kt][0], xal[m][kt][0]);
            split2h(v1, xah[m][kt][1], xal[m][kt][1]);
            split2h(v2, xah[m][kt][2], xal[m][kt][2]);
            split2h(v3, xah[m][kt][3], xal[m][kt][3]);
        }
    }

    const uint2* w1s = reinterpret_cast<const uint2*>(smc + OFF_W1);
    const uint2* w2s = reinterpret_cast<const uint2*>(smc + OFF_W2);

    float acc2[4][2][4];
    #pragma unroll
    for (int n2 = 0; n2 < 4; n2++)
        #pragma unroll
        for (int m = 0; m < 2; m++)
            #pragma unroll
            for (int c = 0; c < 4; c++) acc2[n2][m][c] = 0.0f;

    #pragma unroll 1
    for (int p = 0; p < 8; p++) {
        float a1[2][2][4];
        #pragma unroll
        for (int nt = 0; nt < 2; nt++)
            #pragma unroll
            for (int m = 0; m < 2; m++)
                #pragma unroll
                for (int c = 0; c < 4; c++) a1[nt][m][c] = 0.0f;

        #pragma unroll
        for (int kt = 0; kt < 4; kt++) {
            #pragma unroll
            for (int nt = 0; nt < 2; nt++) {
                int n = p * 16 + nt * 8 + rq;
                uint2 u = w1s[n * 16 + ((kt * 4 + lam) ^ swz)];
                #pragma unroll
                for (int m = 0; m < 2; m++) {
                    mma16816(a1[nt][m], xah[m][kt], u.x, u.y);    // hi * w
                    mma16816(a1[nt][m], xal[m][kt], u.x, u.y);    // lo * w
                }
            }
        }

        float2 bb0 = *reinterpret_cast<const float2*>(smf + OFF_B1 / 4 + p * 16 + 2 * lam);
        float2 bb1 = *reinterpret_cast<const float2*>(smf + OFF_B1 / 4 + p * 16 + 8 + 2 * lam);
        uint32_t a2h[2][4], a2l[2][4];
        #pragma unroll
        for (int m = 0; m < 2; m++) {
            float2 h01 = make_float2(fmaxf(a1[0][m][0] + bb0.x, 0.0f),
                                     fmaxf(a1[0][m][1] + bb0.y, 0.0f));
            float2 h23 = make_float2(fmaxf(a1[0][m][2] + bb0.x, 0.0f),
                                     fmaxf(a1[0][m][3] + bb0.y, 0.0f));
            float2 h45 = make_float2(fmaxf(a1[1][m][0] + bb1.x, 0.0f),
                                     fmaxf(a1[1][m][1] + bb1.y, 0.0f));
            float2 h67 = make_float2(fmaxf(a1[1][m][2] + bb1.x, 0.0f),
                                     fmaxf(a1[1][m][3] + bb1.y, 0.0f));
            split2h(h01, a2h[m][0], a2l[m][0]);
            split2h(h23, a2h[m][1], a2l[m][1]);
            split2h(h45, a2h[m][2], a2l[m][2]);
            split2h(h67, a2h[m][3], a2l[m][3]);
        }

        #pragma unroll
        for (int n2 = 0; n2 < 4; n2++) {
            int n = n2 * 8 + rq;
            uint2 u = w2s[n * 32 + ((p * 4 + lam) ^ swz)];
            #pragma unroll
            for (int m = 0; m < 2; m++) {
                mma16816(acc2[n2][m], a2h[m], u.x, u.y);
                mma16816(acc2[n2][m], a2l[m], u.x, u.y);
            }
        }
    }

    // ---------------- epilogue ----------------
    float2 dv[4][2];
    float2 b2v[4];
    #pragma unroll
    for (int n2 = 0; n2 < 4; n2++) {
        float4 dq = *reinterpret_cast<const float4*>(smf + OFF_DEC / 4 + (n2 * 8 + 2 * lam) * 2);
        dv[n2][0] = make_float2(dq.x, dq.y);
        dv[n2][1] = make_float2(dq.z, dq.w);
        b2v[n2] = *reinterpret_cast<const float2*>(smf + OFF_B2 / 4 + n2 * 8 + 2 * lam);
    }

    __syncwarp();
    const float2* opart = reinterpret_cast<const float2*>(smc + OFF_OP);
    #pragma unroll
    for (int m = 0; m < 2; m++) {
        #pragma unroll
        for (int h = 0; h < 2; h++) {
            float2 o = make_float2(0.0f, 0.0f);
            #pragma unroll
            for (int n2 = 0; n2 < 4; n2++) {
                float v0 = fmaxf(acc2[n2][m][2 * h]     + b2v[n2].x, 0.0f);
                float v1 = fmaxf(acc2[n2][m][2 * h + 1] + b2v[n2].y, 0.0f);
                o = ffma2(make_float2(v0, v0), dv[n2][0], o);
                o = ffma2(make_float2(v1, v1), dv[n2][1], o);
            }
            o.x += __shfl_xor_sync(0xffffffffu, o.x, 1);
            o.y += __shfl_xor_sync(0xffffffffu, o.y, 1);
            o.x += __shfl_xor_sync(0xffffffffu, o.x, 2);
            o.y += __shfl_xor_sync(0xffffffffu, o.y, 2);
            if (lam == 0) {
                int rloc = m0W + m * 16 + h * 8 + rq;
                float2 op = opart[rloc];
                o.x += op.x; o.y += op.y;
                reinterpret_cast<float2*>(out)[rowbase + rloc] = o;
            }
        }
    }
}

extern "C" void kernel_launch(void* const* d_in, const int* in_sizes, int n_in,
                              void* d_out, int out_size)
{
    const float* x         = (const float*)d_in[0];
    const float* norm_mean = (const float*)d_in[1];
    const float* norm_std  = (const float*)d_in[2];
    const float* mlp_w1    = (const float*)d_in[3];
    const float* mlp_b1    = (const float*)d_in[4];
    const float* mlp_w2    = (const float*)d_in[5];
    const float* mlp_b2    = (const float*)d_in[6];
    const float* enc_w     = (const float*)d_in[7];
    const float* enc_b     = (const float*)d_in[8];
    const float* src_w     = (const float*)d_in[9];
    const float* src_b     = (const float*)d_in[10];
    const float* dst_w     = (const float*)d_in[11];
    const float* dst_b     = (const float*)d_in[12];
    const float* dec_w     = (const float*)d_in[13];
    const float* dec_b     = (const float*)d_in[14];

    int nrows = in_sizes[0] / 64;
    int grid = nrows / 128;

    cudaFuncSetAttribute(ggan_mma_kernel, cudaFuncAttributeMaxDynamicSharedMemorySize, SMEM_BYTES);
    ggan_mma_kernel<<<grid, TPB, SMEM_BYTES>>>(x, norm_mean, norm_std,
                                               mlp_w1, mlp_b1, mlp_w2, mlp_b2,
                                               enc_w, enc_b, src_w, src_b, dst_w, dst_b,
                                               dec_w, dec_b, (float*)d_out);
}